// round 8
// baseline (speedup 1.0000x reference)
#include <cuda_runtime.h>
#include <cuda.h>
#include <dlfcn.h>
#include <cstdint>

// GateRecurrent2dnoind: H[h,w] = B*X + G1*H[h-1,w-1] + G2*H[h,w-1] + G3*H[h+1,w-1]
// [16, 32, 128, 128] fp32.
// 1 CTA = 1 plane, 64 threads, 48KB smem -> 4 CTAs/SM -> the whole 512-CTA grid
// is resident in ONE wave (no tail quantization). Thread 0: TMA producer
// (depth-2 ring of 8-col stages x 5 tensors, SWIZZLE_32B). Warp 1: consumer
// shfl scan (lane l owns rows l,l+32,l+64,l+96). Output accumulated in a
// 16-col SW64 buffer, flushed by TMA store every 2 tiles with deferred waits.

#define HH      128
#define WT      8
#define NT      16
#define DEPTH   2
#define SLOT_F  (HH * WT)            // 1024 floats / tensor / stage
#define STAGE_F (5 * SLOT_F)         // 5120 floats = 20KB / stage
#define IN_F    (DEPTH * STAGE_F)    // 10240 floats = 40KB
#define SOUT_F  (HH * 16)            // 2048 floats = 8KB (16-col out batch)
#define SM_F    (IN_F + SOUT_F)
#define BAR_OFF (SM_F * 4)           // 49152
#define SMEM_BYTES (BAR_OFF + 64)    // 49216 -> 4 CTAs/SM
#define STAGE_BYTES (STAGE_F * 4)    // 20480

#define FULLM 0xFFFFFFFFu
#define COMP(v, j) ((j) == 0 ? (v).x : (j) == 1 ? (v).y : (j) == 2 ? (v).z : (v).w)

// ---------------- PTX helpers ----------------
__device__ __forceinline__ void mbar_init(uint32_t a, uint32_t cnt) {
    asm volatile("mbarrier.init.shared.b64 [%0], %1;" :: "r"(a), "r"(cnt) : "memory");
}
__device__ __forceinline__ void mbar_expect_tx(uint32_t a, uint32_t bytes) {
    asm volatile("mbarrier.arrive.expect_tx.shared.b64 _, [%0], %1;"
                 :: "r"(a), "r"(bytes) : "memory");
}
__device__ __forceinline__ void mbar_arrive(uint32_t a) {
    asm volatile("mbarrier.arrive.shared.b64 _, [%0];" :: "r"(a) : "memory");
}
__device__ __forceinline__ void mbar_wait_acq(uint32_t a, uint32_t ph) {
    asm volatile(
        "{\n\t.reg .pred P;\n"
        "W%=:\n\t"
        "mbarrier.try_wait.parity.acquire.cta.shared::cta.b64 P, [%0], %1, 0x989680;\n\t"
        "@P bra D%=;\n\t"
        "bra W%=;\n"
        "D%=:\n\t}"
        :: "r"(a), "r"(ph) : "memory");
}
__device__ __forceinline__ void mbar_wait_rlx(uint32_t a, uint32_t ph) {
    asm volatile(
        "{\n\t.reg .pred P;\n"
        "W%=:\n\t"
        "mbarrier.try_wait.parity.relaxed.cta.shared::cta.b64 P, [%0], %1, 0x989680;\n\t"
        "@P bra D%=;\n\t"
        "bra W%=;\n"
        "D%=:\n\t}"
        :: "r"(a), "r"(ph) : "memory");
}
__device__ __forceinline__ void tma_ld2d(uint32_t smem, const void* map,
                                         int32_t cx, int32_t cy, uint32_t mbar) {
    asm volatile(
        "cp.async.bulk.tensor.2d.shared::cta.global.tile.mbarrier::complete_tx::bytes "
        "[%0], [%1, {%2, %3}], [%4];"
        :: "r"(smem), "l"(map), "r"(cx), "r"(cy), "r"(mbar) : "memory");
}
__device__ __forceinline__ void tma_st2d(const void* map, int32_t cx, int32_t cy,
                                         uint32_t smem) {
    asm volatile(
        "cp.async.bulk.tensor.2d.global.shared::cta.tile.bulk_group "
        "[%0, {%1, %2}], [%3];"
        :: "l"(map), "r"(cx), "r"(cy), "r"(smem) : "memory");
}
__device__ __forceinline__ void tma_st_commit() {
    asm volatile("cp.async.bulk.commit_group;" ::: "memory");
}
__device__ __forceinline__ void tma_st_wait0() {
    asm volatile("cp.async.bulk.wait_group 0;" ::: "memory");
}
__device__ __forceinline__ void fence_async_shared() {
    asm volatile("fence.proxy.async.shared::cta;" ::: "memory");
}

// ---------------- kernel ----------------
__global__ __launch_bounds__(64)
void gaterec2d_w1_kernel(const __grid_constant__ CUtensorMap mX,
                         const __grid_constant__ CUtensorMap mB,
                         const __grid_constant__ CUtensorMap m1,
                         const __grid_constant__ CUtensorMap m2,
                         const __grid_constant__ CUtensorMap m3,
                         const __grid_constant__ CUtensorMap mO)
{
    extern __shared__ float smf[];
    const uint32_t sb = (uint32_t)__cvta_generic_to_shared(smf);
    const int tid = threadIdx.x;
    const int cy  = blockIdx.x * HH;

    const uint32_t fullb  = sb + BAR_OFF;        // full[s]  at +8*s
    const uint32_t emptyb = sb + BAR_OFF + 16;   // empty[s] at +8*s

    if (tid == 0) {
        #pragma unroll
        for (int s = 0; s < DEPTH; ++s) {
            mbar_init(fullb  + 8u * s, 1);
            mbar_init(emptyb + 8u * s, 1);
        }
    }
    __syncthreads();

    if (tid == 0) {
        // ---------------- producer ----------------
        #pragma unroll 1
        for (int t = 0; t < NT; ++t) {
            const int s = t & 1, k = t >> 1;
            mbar_wait_rlx(emptyb + 8u * s, (uint32_t)((k & 1) ^ 1));
            mbar_expect_tx(fullb + 8u * s, STAGE_BYTES);
            const uint32_t slot = sb + (uint32_t)(s * STAGE_F) * 4u;
            const int cx = WT * t;
            tma_ld2d(slot + 0u * SLOT_F * 4u, &mX, cx, cy, fullb + 8u * s);
            tma_ld2d(slot + 1u * SLOT_F * 4u, &mB, cx, cy, fullb + 8u * s);
            tma_ld2d(slot + 2u * SLOT_F * 4u, &m1, cx, cy, fullb + 8u * s);
            tma_ld2d(slot + 3u * SLOT_F * 4u, &m2, cx, cy, fullb + 8u * s);
            tma_ld2d(slot + 4u * SLOT_F * 4u, &m3, cx, cy, fullb + 8u * s);
        }
    } else if (tid >= 32) {
        // ---------------- consumer (warp 1) ----------------
        const int l    = tid & 31;
        const int insw = (l >> 2) & 1;   // SW32 input swizzle bit (lane-constant)
        const int outw = (l >> 1) & 3;   // SW64 output swizzle (lane-constant)
        float* sout = smf + IN_F;

        float h0 = 0.f, h1 = 0.f, h2 = 0.f, h3 = 0.f;

        #pragma unroll 1
        for (int t = 0; t < NT; ++t) {
            const int s = t & 1, k = t >> 1;
            mbar_wait_acq(fullb + 8u * s, (uint32_t)(k & 1));

            // before overwriting the out batch (even t >= 2): drain prior store
            if (((t & 1) == 0) && t >= 2) { if (l == 0) tma_st_wait0(); }
            __syncwarp();

            const float* bx = smf + s * STAGE_F;           // X
            const float* bb = bx + SLOT_F;                 // B
            const float* b1 = bb + SLOT_F;                 // G1
            const float* b2 = b1 + SLOT_F;                 // G2
            const float* b3 = b2 + SLOT_F;                 // G3

            #pragma unroll
            for (int g = 0; g < 2; ++g) {
                const int gs = g ^ insw;     // SW32: 16B halves swap by row bit 2
                float4 xv[4], bv[4], a1[4], a2[4], a3[4];
                #pragma unroll
                for (int q = 0; q < 4; ++q) {
                    const int off = (l + 32 * q) * WT + 4 * gs;
                    xv[q] = *(const float4*)(bx + off);
                    bv[q] = *(const float4*)(bb + off);
                    a1[q] = *(const float4*)(b1 + off);
                    a2[q] = *(const float4*)(b2 + off);
                    a3[q] = *(const float4*)(b3 + off);
                }

                float ov[4][4];
                #pragma unroll
                for (int j = 0; j < 4; ++j) {
                    const float bx0 = COMP(bv[0], j) * COMP(xv[0], j);
                    const float bx1 = COMP(bv[1], j) * COMP(xv[1], j);
                    const float bx2 = COMP(bv[2], j) * COMP(xv[2], j);
                    const float bx3 = COMP(bv[3], j) * COMP(xv[3], j);

                    const float u0 = __shfl_sync(FULLM, (l == 31) ? 0.f : h0, (l + 31) & 31);
                    const float u1 = __shfl_sync(FULLM, (l == 31) ? h0  : h1, (l + 31) & 31);
                    const float u2 = __shfl_sync(FULLM, (l == 31) ? h1  : h2, (l + 31) & 31);
                    const float u3 = __shfl_sync(FULLM, (l == 31) ? h2  : h3, (l + 31) & 31);
                    const float d0 = __shfl_sync(FULLM, (l == 0) ? h1  : h0, (l + 1) & 31);
                    const float d1 = __shfl_sync(FULLM, (l == 0) ? h2  : h1, (l + 1) & 31);
                    const float d2 = __shfl_sync(FULLM, (l == 0) ? h3  : h2, (l + 1) & 31);
                    const float d3 = __shfl_sync(FULLM, (l == 0) ? 0.f : h3, (l + 1) & 31);

                    h0 = fmaf(COMP(a1[0], j), u0, fmaf(COMP(a2[0], j), h0, fmaf(COMP(a3[0], j), d0, bx0)));
                    h1 = fmaf(COMP(a1[1], j), u1, fmaf(COMP(a2[1], j), h1, fmaf(COMP(a3[1], j), d1, bx1)));
                    h2 = fmaf(COMP(a1[2], j), u2, fmaf(COMP(a2[2], j), h2, fmaf(COMP(a3[2], j), d2, bx2)));
                    h3 = fmaf(COMP(a1[3], j), u3, fmaf(COMP(a2[3], j), h3, fmaf(COMP(a3[3], j), d3, bx3)));

                    ov[0][j] = h0; ov[1][j] = h1; ov[2][j] = h2; ov[3][j] = h3;
                }

                // write into 16-col out batch; local group G = (t&1)*2+g; SW64
                const int G  = (t & 1) * 2 + g;
                const int sg = G ^ outw;
                #pragma unroll
                for (int q = 0; q < 4; ++q) {
                    const int row = l + 32 * q;
                    float4 v;
                    v.x = ov[q][0]; v.y = ov[q][1]; v.z = ov[q][2]; v.w = ov[q][3];
                    *(float4*)(sout + row * 16 + 4 * sg) = v;
                }
            }

            __syncwarp();
            if (l == 0) {
                mbar_arrive(emptyb + 8u * s);           // stage consumed
                if (t & 1) {                            // flush 16-col batch
                    fence_async_shared();
                    tma_st2d(&mO, (t >> 1) * 16, cy, sb + (uint32_t)IN_F * 4u);
                    tma_st_commit();                    // wait deferred to next even t
                }
            }
        }
        if (l == 0) tma_st_wait0();   // drain final store
    }
}

// ---------------- host ----------------
extern "C" void kernel_launch(void* const* d_in, const int* in_sizes, int n_in,
                              void* d_out, int out_size)
{
    typedef CUresult (*EncFn)(CUtensorMap*, CUtensorMapDataType, cuuint32_t, void*,
                              const cuuint64_t*, const cuuint64_t*, const cuuint32_t*,
                              const cuuint32_t*, CUtensorMapInterleave, CUtensorMapSwizzle,
                              CUtensorMapL2promotion, CUtensorMapFloatOOBfill);
    void* h = dlopen("libcuda.so.1", RTLD_NOW | RTLD_GLOBAL);
    if (!h) h = dlopen("libcuda.so", RTLD_NOW | RTLD_GLOBAL);
    EncFn enc = (EncFn)dlsym(h, "cuTensorMapEncodeTiled");

    const cuuint64_t gdim[2]    = {128, 512ull * 128};   // [w, plane*128 + h]
    const cuuint64_t gstride[1] = {512};                 // 128 floats * 4B
    const cuuint32_t estr[2]    = {1, 1};
    const cuuint32_t box_in[2]  = {WT, 128};             // 32B rows -> SW32
    const cuuint32_t box_out[2] = {16, 128};             // 64B rows -> SW64

    CUtensorMap maps[5];
    for (int i = 0; i < 5; ++i) {
        enc(&maps[i], CU_TENSOR_MAP_DATA_TYPE_FLOAT32, 2, (void*)d_in[i],
            gdim, gstride, box_in, estr,
            CU_TENSOR_MAP_INTERLEAVE_NONE, CU_TENSOR_MAP_SWIZZLE_32B,
            CU_TENSOR_MAP_L2_PROMOTION_L2_128B, CU_TENSOR_MAP_FLOAT_OOB_FILL_NONE);
    }
    CUtensorMap mO;
    enc(&mO, CU_TENSOR_MAP_DATA_TYPE_FLOAT32, 2, d_out,
        gdim, gstride, box_out, estr,
        CU_TENSOR_MAP_INTERLEAVE_NONE, CU_TENSOR_MAP_SWIZZLE_64B,
        CU_TENSOR_MAP_L2_PROMOTION_L2_128B, CU_TENSOR_MAP_FLOAT_OOB_FILL_NONE);

    cudaFuncSetAttribute(gaterec2d_w1_kernel,
                         cudaFuncAttributeMaxDynamicSharedMemorySize, SMEM_BYTES);

    gaterec2d_w1_kernel<<<512, 64, SMEM_BYTES>>>(maps[0], maps[1], maps[2],
                                                 maps[3], maps[4], mO);
}

// round 9
// speedup vs baseline: 1.0861x; 1.0861x over previous
#include <cuda_runtime.h>
#include <cuda.h>
#include <dlfcn.h>
#include <cstdint>

// GateRecurrent2dnoind: H[h,w] = B*X + G1*H[h-1,w-1] + G2*H[h,w-1] + G3*H[h+1,w-1]
// [16, 32, 128, 128] fp32.
// Persistent CTA owns TWO planes (grid 256, 2 CTAs/SM -> one wave, uniform
// balance). 64 threads: thread 0 = TMA producer running a seamless depth-2
// ring across both planes (16-col stages x 5 tensors, SWIZZLE_64B). Warp 1 =
// consumer shfl scan (lane l owns rows l,l+32,l+64,l+96; h-state reset at the
// plane switch). Output double-buffered (2 x 16 cols), TMA store with deferred
// wait_group. All bulk traffic bypasses the L1tex fill path.

#define HH      128
#define WT      16
#define NTP     8                    // tiles per plane
#define NPL     2                    // planes per CTA
#define NTS     (NTP * NPL)          // 16 total stages
#define DEPTH   2
#define SLOT_F  (HH * WT)            // 2048 floats / tensor / stage
#define STAGE_F (5 * SLOT_F)         // 10240 floats = 40KB / stage
#define IN_F    (DEPTH * STAGE_F)    // 20480 floats = 80KB
#define OUTBUF_F (HH * WT)           // 2048 floats per out buffer
#define SM_F    (IN_F + 2 * OUTBUF_F)
#define BAR_OFF (SM_F * 4)
#define SMEM_BYTES (BAR_OFF + 64)    // ~96.3KB -> 2 CTAs/SM
#define STAGE_BYTES (STAGE_F * 4)    // 40960

#define FULLM 0xFFFFFFFFu
#define COMP(v, j) ((j) == 0 ? (v).x : (j) == 1 ? (v).y : (j) == 2 ? (v).z : (v).w)

// ---------------- PTX helpers ----------------
__device__ __forceinline__ void mbar_init(uint32_t a, uint32_t cnt) {
    asm volatile("mbarrier.init.shared.b64 [%0], %1;" :: "r"(a), "r"(cnt) : "memory");
}
__device__ __forceinline__ void mbar_expect_tx(uint32_t a, uint32_t bytes) {
    asm volatile("mbarrier.arrive.expect_tx.shared.b64 _, [%0], %1;"
                 :: "r"(a), "r"(bytes) : "memory");
}
__device__ __forceinline__ void mbar_arrive(uint32_t a) {
    asm volatile("mbarrier.arrive.shared.b64 _, [%0];" :: "r"(a) : "memory");
}
__device__ __forceinline__ void mbar_wait_acq(uint32_t a, uint32_t ph) {
    asm volatile(
        "{\n\t.reg .pred P;\n"
        "W%=:\n\t"
        "mbarrier.try_wait.parity.acquire.cta.shared::cta.b64 P, [%0], %1, 0x989680;\n\t"
        "@P bra D%=;\n\t"
        "bra W%=;\n"
        "D%=:\n\t}"
        :: "r"(a), "r"(ph) : "memory");
}
__device__ __forceinline__ void mbar_wait_rlx(uint32_t a, uint32_t ph) {
    asm volatile(
        "{\n\t.reg .pred P;\n"
        "W%=:\n\t"
        "mbarrier.try_wait.parity.relaxed.cta.shared::cta.b64 P, [%0], %1, 0x989680;\n\t"
        "@P bra D%=;\n\t"
        "bra W%=;\n"
        "D%=:\n\t}"
        :: "r"(a), "r"(ph) : "memory");
}
__device__ __forceinline__ void tma_ld2d(uint32_t smem, const void* map,
                                         int32_t cx, int32_t cy, uint32_t mbar) {
    asm volatile(
        "cp.async.bulk.tensor.2d.shared::cta.global.tile.mbarrier::complete_tx::bytes "
        "[%0], [%1, {%2, %3}], [%4];"
        :: "r"(smem), "l"(map), "r"(cx), "r"(cy), "r"(mbar) : "memory");
}
__device__ __forceinline__ void tma_st2d(const void* map, int32_t cx, int32_t cy,
                                         uint32_t smem) {
    asm volatile(
        "cp.async.bulk.tensor.2d.global.shared::cta.tile.bulk_group "
        "[%0, {%1, %2}], [%3];"
        :: "l"(map), "r"(cx), "r"(cy), "r"(smem) : "memory");
}
__device__ __forceinline__ void tma_st_commit() {
    asm volatile("cp.async.bulk.commit_group;" ::: "memory");
}
__device__ __forceinline__ void tma_st_wait1() {
    asm volatile("cp.async.bulk.wait_group 1;" ::: "memory");
}
__device__ __forceinline__ void tma_st_wait0() {
    asm volatile("cp.async.bulk.wait_group 0;" ::: "memory");
}
__device__ __forceinline__ void fence_async_shared() {
    asm volatile("fence.proxy.async.shared::cta;" ::: "memory");
}

// ---------------- kernel ----------------
__global__ __launch_bounds__(64)
void gaterec2d_p2_kernel(const __grid_constant__ CUtensorMap mX,
                         const __grid_constant__ CUtensorMap mB,
                         const __grid_constant__ CUtensorMap m1,
                         const __grid_constant__ CUtensorMap m2,
                         const __grid_constant__ CUtensorMap m3,
                         const __grid_constant__ CUtensorMap mO)
{
    extern __shared__ float smf[];
    const uint32_t sb = (uint32_t)__cvta_generic_to_shared(smf);
    const int tid = threadIdx.x;
    const int plane0 = blockIdx.x * NPL;

    const uint32_t fullb  = sb + BAR_OFF;        // full[s]  at +8*s
    const uint32_t emptyb = sb + BAR_OFF + 16;   // empty[s] at +8*s

    if (tid == 0) {
        #pragma unroll
        for (int s = 0; s < DEPTH; ++s) {
            mbar_init(fullb  + 8u * s, 1);
            mbar_init(emptyb + 8u * s, 1);
        }
    }
    __syncthreads();

    if (tid == 0) {
        // ---------------- producer: seamless ring across both planes ----------------
        #pragma unroll 1
        for (int ts = 0; ts < NTS; ++ts) {
            const int s = ts & 1, k = ts >> 1;
            const int p = ts >> 3;               // plane within CTA
            const int t = ts & 7;                // tile within plane
            mbar_wait_rlx(emptyb + 8u * s, (uint32_t)((k & 1) ^ 1));
            mbar_expect_tx(fullb + 8u * s, STAGE_BYTES);
            const uint32_t slot = sb + (uint32_t)(s * STAGE_F) * 4u;
            const int cx = WT * t;
            const int cy = (plane0 + p) * HH;
            tma_ld2d(slot + 0u * SLOT_F * 4u, &mX, cx, cy, fullb + 8u * s);
            tma_ld2d(slot + 1u * SLOT_F * 4u, &mB, cx, cy, fullb + 8u * s);
            tma_ld2d(slot + 2u * SLOT_F * 4u, &m1, cx, cy, fullb + 8u * s);
            tma_ld2d(slot + 3u * SLOT_F * 4u, &m2, cx, cy, fullb + 8u * s);
            tma_ld2d(slot + 4u * SLOT_F * 4u, &m3, cx, cy, fullb + 8u * s);
        }
    } else if (tid >= 32) {
        // ---------------- consumer (warp 1) ----------------
        const int l   = tid & 31;
        const int lsw = (l >> 1) & 3;   // SW64 swizzle term (lane-constant for owned rows)

        float h0 = 0.f, h1 = 0.f, h2 = 0.f, h3 = 0.f;

        #pragma unroll 1
        for (int ts = 0; ts < NTS; ++ts) {
            const int s = ts & 1, k = ts >> 1;
            const int p = ts >> 3;
            const int t = ts & 7;
            if (t == 0) { h0 = 0.f; h1 = 0.f; h2 = 0.f; h3 = 0.f; }  // new plane

            mbar_wait_acq(fullb + 8u * s, (uint32_t)(k & 1));

            // out buffer (ts&1) reused every 2 stages: drain store from ts-2
            if (ts >= 2) { if (l == 0) tma_st_wait1(); }
            __syncwarp();

            const float* bx = smf + s * STAGE_F;
            const float* bb = bx + SLOT_F;
            const float* b1 = bb + SLOT_F;
            const float* b2 = b1 + SLOT_F;
            const float* b3 = b2 + SLOT_F;
            float* sout = smf + IN_F + (ts & 1) * OUTBUF_F;

            #pragma unroll
            for (int g = 0; g < 4; ++g) {
                const int gs = g ^ lsw;          // SW64: 16B slot within 64B row
                float4 xv[4], bv[4], a1[4], a2[4], a3[4];
                #pragma unroll
                for (int q = 0; q < 4; ++q) {
                    const int off = (l + 32 * q) * WT + 4 * gs;
                    xv[q] = *(const float4*)(bx + off);
                    bv[q] = *(const float4*)(bb + off);
                    a1[q] = *(const float4*)(b1 + off);
                    a2[q] = *(const float4*)(b2 + off);
                    a3[q] = *(const float4*)(b3 + off);
                }

                float ov[4][4];
                #pragma unroll
                for (int j = 0; j < 4; ++j) {
                    const float bx0 = COMP(bv[0], j) * COMP(xv[0], j);
                    const float bx1 = COMP(bv[1], j) * COMP(xv[1], j);
                    const float bx2 = COMP(bv[2], j) * COMP(xv[2], j);
                    const float bx3 = COMP(bv[3], j) * COMP(xv[3], j);

                    const float u0 = __shfl_sync(FULLM, (l == 31) ? 0.f : h0, (l + 31) & 31);
                    const float u1 = __shfl_sync(FULLM, (l == 31) ? h0  : h1, (l + 31) & 31);
                    const float u2 = __shfl_sync(FULLM, (l == 31) ? h1  : h2, (l + 31) & 31);
                    const float u3 = __shfl_sync(FULLM, (l == 31) ? h2  : h3, (l + 31) & 31);
                    const float d0 = __shfl_sync(FULLM, (l == 0) ? h1  : h0, (l + 1) & 31);
                    const float d1 = __shfl_sync(FULLM, (l == 0) ? h2  : h1, (l + 1) & 31);
                    const float d2 = __shfl_sync(FULLM, (l == 0) ? h3  : h2, (l + 1) & 31);
                    const float d3 = __shfl_sync(FULLM, (l == 0) ? 0.f : h3, (l + 1) & 31);

                    h0 = fmaf(COMP(a1[0], j), u0, fmaf(COMP(a2[0], j), h0, fmaf(COMP(a3[0], j), d0, bx0)));
                    h1 = fmaf(COMP(a1[1], j), u1, fmaf(COMP(a2[1], j), h1, fmaf(COMP(a3[1], j), d1, bx1)));
                    h2 = fmaf(COMP(a1[2], j), u2, fmaf(COMP(a2[2], j), h2, fmaf(COMP(a3[2], j), d2, bx2)));
                    h3 = fmaf(COMP(a1[3], j), u3, fmaf(COMP(a2[3], j), h3, fmaf(COMP(a3[3], j), d3, bx3)));

                    ov[0][j] = h0; ov[1][j] = h1; ov[2][j] = h2; ov[3][j] = h3;
                }

                #pragma unroll
                for (int q = 0; q < 4; ++q) {
                    const int row = l + 32 * q;
                    float4 v;
                    v.x = ov[q][0]; v.y = ov[q][1]; v.z = ov[q][2]; v.w = ov[q][3];
                    *(float4*)(sout + row * WT + 4 * gs) = v;
                }
            }

            __syncwarp();
            if (l == 0) {
                mbar_arrive(emptyb + 8u * s);    // stage consumed
                fence_async_shared();
                tma_st2d(&mO, WT * t, (plane0 + p) * HH,
                         sb + (uint32_t)(IN_F + (ts & 1) * OUTBUF_F) * 4u);
                tma_st_commit();                 // wait deferred 2 stages
            }
        }
        if (l == 0) tma_st_wait0();              // drain before exit
    }
}

// ---------------- host ----------------
extern "C" void kernel_launch(void* const* d_in, const int* in_sizes, int n_in,
                              void* d_out, int out_size)
{
    typedef CUresult (*EncFn)(CUtensorMap*, CUtensorMapDataType, cuuint32_t, void*,
                              const cuuint64_t*, const cuuint64_t*, const cuuint32_t*,
                              const cuuint32_t*, CUtensorMapInterleave, CUtensorMapSwizzle,
                              CUtensorMapL2promotion, CUtensorMapFloatOOBfill);
    void* h = dlopen("libcuda.so.1", RTLD_NOW | RTLD_GLOBAL);
    if (!h) h = dlopen("libcuda.so", RTLD_NOW | RTLD_GLOBAL);
    EncFn enc = (EncFn)dlsym(h, "cuTensorMapEncodeTiled");

    const cuuint64_t gdim[2]    = {128, 512ull * 128};   // [w, plane*128 + h]
    const cuuint64_t gstride[1] = {512};                 // 128 floats * 4B
    const cuuint32_t estr[2]    = {1, 1};
    const cuuint32_t box[2]     = {WT, 128};             // 64B rows -> SW64

    CUtensorMap maps[5];
    for (int i = 0; i < 5; ++i) {
        enc(&maps[i], CU_TENSOR_MAP_DATA_TYPE_FLOAT32, 2, (void*)d_in[i],
            gdim, gstride, box, estr,
            CU_TENSOR_MAP_INTERLEAVE_NONE, CU_TENSOR_MAP_SWIZZLE_64B,
            CU_TENSOR_MAP_L2_PROMOTION_L2_128B, CU_TENSOR_MAP_FLOAT_OOB_FILL_NONE);
    }
    CUtensorMap mO;
    enc(&mO, CU_TENSOR_MAP_DATA_TYPE_FLOAT32, 2, d_out,
        gdim, gstride, box, estr,
        CU_TENSOR_MAP_INTERLEAVE_NONE, CU_TENSOR_MAP_SWIZZLE_64B,
        CU_TENSOR_MAP_L2_PROMOTION_L2_128B, CU_TENSOR_MAP_FLOAT_OOB_FILL_NONE);

    cudaFuncSetAttribute(gaterec2d_p2_kernel,
                         cudaFuncAttributeMaxDynamicSharedMemorySize, SMEM_BYTES);

    gaterec2d_p2_kernel<<<256, 64, SMEM_BYTES>>>(maps[0], maps[1], maps[2],
                                                 maps[3], maps[4], mO);
}